// round 11
// baseline (speedup 1.0000x reference)
#include <cuda_runtime.h>
#include <cuda_bf16.h>
#include <math.h>
#include <stdint.h>

#define Bb 128
#define Ss 256
#define Ii 512
#define Oo 512
#define Hh 1024
#define Gg (3*Hh)      // 3072
#define IOio (Ii+Oo)   // 1024

// ---- output layout ----
#define PROBS_OFF  0
#define PRE_OFF    ((size_t)Bb*Ss*Oo)
#define SAMP_OFF   (PRE_OFF + (size_t)Bb*Ss*Hh)
#define HX_OFF     (SAMP_OFF + (size_t)Bb*Ss*Oo)

// ---- scratch ----
__device__ int   g_idx[Bb*Ss];
__device__ float g_gi[(size_t)Ss*Bb*Gg];
__device__ float g_h[Bb*Hh];
__device__ float g_ghp[3][(size_t)Bb*Gg];
__device__ float g_hs[(size_t)Bb*Ss*Hh];
__device__ float g_logits[(size_t)Bb*Ss*Oo];
__device__ __nv_bfloat16 g_h1[Bb*Hh];
__device__ __nv_bfloat16 g_h2[Bb*Hh];
__device__ __nv_bfloat16 g_h3[Bb*Hh];
__device__ __nv_bfloat16 g_w1[(size_t)Gg*Hh];
__device__ __nv_bfloat16 g_w2[(size_t)Gg*Hh];
__device__ __nv_bfloat16 g_w3[(size_t)Gg*Hh];

// product table: seg -> (A split idx, B split idx)
__constant__ int SEG_A[6] = {0,0,1,0,2,1};
__constant__ int SEG_B[6] = {0,1,0,2,0,1};

// ============================================================
// PTX helpers
// ============================================================
__device__ __forceinline__ uint32_t smem_u32(const void* p) {
    uint32_t a;
    asm("{ .reg .u64 t; cvta.to.shared.u64 t, %1; cvt.u32.u64 %0, t; }" : "=r"(a) : "l"(p));
    return a;
}
__device__ __forceinline__ void cp16(uint32_t dst, const void* src) {
    asm volatile("cp.async.cg.shared.global [%0], [%1], 16;" :: "r"(dst), "l"(src));
}
#define CP_COMMIT() asm volatile("cp.async.commit_group;" ::: "memory")
#define CP_WAIT(n)  asm volatile("cp.async.wait_group %0;" :: "n"(n) : "memory")

__device__ __forceinline__ void ldmA(uint32_t* a, uint32_t addr) {
    asm volatile("ldmatrix.sync.aligned.m8n8.x4.shared.b16 {%0,%1,%2,%3}, [%4];"
        : "=r"(a[0]), "=r"(a[1]), "=r"(a[2]), "=r"(a[3]) : "r"(addr));
}
__device__ __forceinline__ void ldmB4(uint32_t* b, uint32_t addr) {
    asm volatile("ldmatrix.sync.aligned.m8n8.x4.shared.b16 {%0,%1,%2,%3}, [%4];"
        : "=r"(b[0]), "=r"(b[1]), "=r"(b[2]), "=r"(b[3]) : "r"(addr));
}
__device__ __forceinline__ void mma_bf16(float* c, const uint32_t* a, const uint32_t* b) {
    asm volatile("mma.sync.aligned.m16n8k16.row.col.f32.bf16.bf16.f32 "
        "{%0,%1,%2,%3}, {%4,%5,%6,%7}, {%8,%9}, {%0,%1,%2,%3};"
        : "+f"(c[0]), "+f"(c[1]), "+f"(c[2]), "+f"(c[3])
        : "r"(a[0]), "r"(a[1]), "r"(a[2]), "r"(a[3]), "r"(b[0]), "r"(b[1]));
}

#define STRD 80                        // smem row stride (64B data + 16B pad)
#define STAGE_BYTES ((128+128)*STRD)   // 20480 per pipeline stage (A128 + B128 rows)
#define NSTAGE 5

// One BK=32 chunk, warp tile 32(M) x 64(N); 8 warps = 4M x 2N over 128x128.
// All loads hoisted ahead of all mmas; per-element K order identical to R5.
__device__ __forceinline__ void compute_chunk(uint32_t aB, uint32_t bB, int wm, int wn,
                                              int lane, float acc[2][8][4]) {
    uint32_t a[2][2][4], b[2][4][4];
    int t = lane >> 3, r = lane & 7;
    #pragma unroll
    for (int kk = 0; kk < 2; kk++) {
        #pragma unroll
        for (int mt = 0; mt < 2; mt++)
            ldmA(a[kk][mt], aB + (wm + mt*16 + (lane & 15))*STRD + kk*32 + ((lane >> 4) & 1)*16);
        // packed B: each x4 covers 2 n-tiles (16 cols) x 2 k-halves
        #pragma unroll
        for (int ldi = 0; ldi < 4; ldi++)
            ldmB4(b[kk][ldi], bB + (wn + ldi*16 + (t >> 1)*8 + r)*STRD + kk*32 + (t & 1)*16);
    }
    #pragma unroll
    for (int kk = 0; kk < 2; kk++)
        #pragma unroll
        for (int mt = 0; mt < 2; mt++)
            #pragma unroll
            for (int nt = 0; nt < 8; nt++)
                mma_bf16(acc[mt][nt], a[kk][mt], &b[kk][nt >> 1][(nt & 1)*2]);
}

// ============================================================
// prep kernels
// ============================================================
__global__ void k_idx(const float* __restrict__ gt, const float* __restrict__ gotoken) {
    int wg   = (blockIdx.x * blockDim.x + threadIdx.x) >> 5;
    int lane = threadIdx.x & 31;
    if (wg >= Bb*Ss) return;
    int s = wg / Bb, b = wg % Bb;
    const float* src = (s == 0) ? gotoken : (gt + ((size_t)b*Ss + (s-1))*Oo);
    int found = Oo;
    for (int o = lane; o < Oo; o += 32)
        if (src[o] > 0.5f) found = min(found, o);
    #pragma unroll
    for (int off = 16; off; off >>= 1)
        found = min(found, __shfl_xor_sync(0xffffffffu, found, off));
    if (lane == 0) g_idx[wg] = found;
}

__device__ __forceinline__ void split3(float v, __nv_bfloat16& a, __nv_bfloat16& b, __nv_bfloat16& c) {
    a = __float2bfloat16(v);
    float r = v - __bfloat162float(a);
    b = __float2bfloat16(r);
    c = __float2bfloat16(r - __bfloat162float(b));
}

__global__ void k_copyh(const float* __restrict__ hx) {
    int i = blockIdx.x * blockDim.x + threadIdx.x;
    if (i < Bb*Hh) {
        float v = hx[i];
        g_h[i] = v;
        split3(v, g_h1[i], g_h2[i], g_h3[i]);
    }
}
__global__ void k_split_w(const float* __restrict__ w) {
    int i = blockIdx.x * blockDim.x + threadIdx.x;
    if (i < Gg*Hh) split3(w[i], g_w1[i], g_w2[i], g_w3[i]);
}

// ============================================================
// 2) gi GEMM (fp32, 128x128 tile, 8x8/thread; per-element k-order = R5)
//    grid (24, 256)
// ============================================================
__global__ __launch_bounds__(256) void k_gemm_gi(const float* __restrict__ y,
                                                 const float* __restrict__ wih,
                                                 const float* __restrict__ bih) {
    __shared__ float As[16][128+4];
    __shared__ float Bs[16][128+4];
    int s  = blockIdx.y;
    int n0 = blockIdx.x * 128;
    int tid = threadIdx.x;
    int tx = tid & 15, ty = tid >> 4;
    float acc[8][8] = {};
    int arow = tid >> 2;          // 0..63 base (2 rows per thread via i-loop)
    int acol = (tid & 3) * 4;

    float4 pa[2], pb[2];
    #pragma unroll
    for (int i = 0; i < 2; i++) {
        pa[i] = *(const float4*)(y + ((size_t)(arow + i*64)*Ss + s)*Ii + acol);
        pb[i] = *(const float4*)(wih + (size_t)(n0 + arow + i*64)*IOio + acol);
    }

    for (int k0 = 0; k0 < Ii; k0 += 16) {
        #pragma unroll
        for (int i = 0; i < 2; i++) {
            int rr = arow + i*64;
            As[acol+0][rr] = pa[i].x; As[acol+1][rr] = pa[i].y;
            As[acol+2][rr] = pa[i].z; As[acol+3][rr] = pa[i].w;
            Bs[acol+0][rr] = pb[i].x; Bs[acol+1][rr] = pb[i].y;
            Bs[acol+2][rr] = pb[i].z; Bs[acol+3][rr] = pb[i].w;
        }
        __syncthreads();
        if (k0 + 16 < Ii) {
            #pragma unroll
            for (int i = 0; i < 2; i++) {
                pa[i] = *(const float4*)(y + ((size_t)(arow + i*64)*Ss + s)*Ii + k0 + 16 + acol);
                pb[i] = *(const float4*)(wih + (size_t)(n0 + arow + i*64)*IOio + k0 + 16 + acol);
            }
        }
        #pragma unroll
        for (int k = 0; k < 16; k++) {
            float ar[8], br[8];
            #pragma unroll
            for (int i2 = 0; i2 < 8; i2++) ar[i2] = As[k][ty*8+i2];
            #pragma unroll
            for (int j = 0; j < 8; j++)   br[j]  = Bs[k][tx*8+j];
            #pragma unroll
            for (int i2 = 0; i2 < 8; i2++)
                #pragma unroll
                for (int j = 0; j < 8; j++) acc[i2][j] += ar[i2]*br[j];
        }
        __syncthreads();
    }
    #pragma unroll
    for (int i2 = 0; i2 < 8; i2++) {
        int b = ty*8 + i2;
        int m = s*Bb + b;
        int id = g_idx[m];
        #pragma unroll
        for (int j = 0; j < 8; j++) {
            int gg = n0 + tx*8 + j;
            g_gi[(size_t)m*Gg + gg] = acc[i2][j] + wih[(size_t)gg*IOio + Ii + id] + bih[gg];
        }
    }
}

// ============================================================
// 3) per-step hidden GEMM (bf16 6-product, split-K=3): grid (24,3)
//    BM=128, BN=128, BK=32; 5-stage cp.async; K order identical to R5
// ============================================================
__global__ __launch_bounds__(256) void k_gemm_gh_mma() {
    extern __shared__ __align__(16) char dyn[];
    int tid = threadIdx.x, wid = tid >> 5, lane = tid & 31;
    int n0 = blockIdx.x * 128;
    int z  = blockIdx.y;
    int wm = (wid >> 1) * 32, wn = (wid & 1) * 64;
    uint32_t sb = smem_u32(dyn);
    const __nv_bfloat16* Ahs[3] = { g_h1, g_h2, g_h3 };
    const __nv_bfloat16* Bws[3] = { g_w1, g_w2, g_w3 };

    auto issue = [&](int c) {
        int buf = c % NSTAGE;
        uint32_t aBuf = sb + buf*STAGE_BYTES;
        uint32_t bBuf = aBuf + 128*STRD;
        int cg  = z*64 + c;
        int seg = cg >> 5;
        int kl  = (cg & 31) << 5;
        const __nv_bfloat16* sa  = Ahs[SEG_A[seg]];
        const __nv_bfloat16* sbw = Bws[SEG_B[seg]];
        #pragma unroll
        for (int i = 0; i < 2; i++) {
            int idx = i*256 + tid;
            int row = idx >> 2, q = idx & 3;
            cp16(aBuf + row*STRD + q*16, sa + (size_t)row*Hh + kl + q*8);
            cp16(bBuf + row*STRD + q*16, sbw + (size_t)(n0 + row)*Hh + kl + q*8);
        }
    };

    float acc[2][8][4] = {};
    issue(0); CP_COMMIT();
    issue(1); CP_COMMIT();
    issue(2); CP_COMMIT();
    issue(3); CP_COMMIT();
    for (int c = 0; c < 64; c++) {
        CP_WAIT(3);
        __syncthreads();
        if (c + 4 < 64) { issue(c + 4); CP_COMMIT(); }
        int buf = c % NSTAGE;
        compute_chunk(sb + buf*STAGE_BYTES, sb + buf*STAGE_BYTES + 128*STRD, wm, wn, lane, acc);
    }

    float* dst = g_ghp[z];
    int quad = lane >> 2, tq = lane & 3;
    #pragma unroll
    for (int mt = 0; mt < 2; mt++) {
        #pragma unroll
        for (int nt = 0; nt < 8; nt++) {
            int row = wm + mt*16 + quad;
            int col = n0 + wn + nt*8 + tq*2;
            *(float2*)(dst + (size_t)row*Gg + col)     = make_float2(acc[mt][nt][0], acc[mt][nt][1]);
            *(float2*)(dst + (size_t)(row+8)*Gg + col) = make_float2(acc[mt][nt][2], acc[mt][nt][3]);
        }
    }
}

// ============================================================
// 4) per-step GRU gate update (float4 vectorized; per-element math = R5)
// ============================================================
__global__ __launch_bounds__(256) void k_update(int s, const float* __restrict__ bhh,
                                                float* __restrict__ out_pre) {
    int i4 = blockIdx.x * blockDim.x + threadIdx.x;
    if (i4 >= Bb*Hh/4) return;
    int i = i4 * 4;
    int b = i / Hh, hh = i % Hh;
    size_t gib = ((size_t)(s*Bb + b))*Gg + hh;
    float4 ir4 = __ldg((const float4*)(g_gi + gib));
    float4 iz4 = __ldg((const float4*)(g_gi + gib + Hh));
    float4 in4 = __ldg((const float4*)(g_gi + gib + 2*Hh));
    size_t ghb = (size_t)b*Gg + hh;
    float4 r0 = __ldcg((const float4*)(g_ghp[0] + ghb));
    float4 r1 = __ldcg((const float4*)(g_ghp[1] + ghb));
    float4 r2 = __ldcg((const float4*)(g_ghp[2] + ghb));
    float4 z0 = __ldcg((const float4*)(g_ghp[0] + ghb + Hh));
    float4 z1 = __ldcg((const float4*)(g_ghp[1] + ghb + Hh));
    float4 z2 = __ldcg((const float4*)(g_ghp[2] + ghb + Hh));
    float4 n0 = __ldcg((const float4*)(g_ghp[0] + ghb + 2*Hh));
    float4 n1 = __ldcg((const float4*)(g_ghp[1] + ghb + 2*Hh));
    float4 n2 = __ldcg((const float4*)(g_ghp[2] + ghb + 2*Hh));
    float4 br4 = __ldg((const float4*)(bhh + hh));
    float4 bz4 = __ldg((const float4*)(bhh + Hh + hh));
    float4 bn4 = __ldg((const float4*)(bhh + 2*Hh + hh));
    float4 h4  = *(const float4*)(g_h + i);

    float ir[4] = {ir4.x, ir4.y, ir4.z, ir4.w};
    float iz[4] = {iz4.x, iz4.y, iz4.z, iz4.w};
    float in_[4] = {in4.x, in4.y, in4.z, in4.w};
    float hr[4] = {(r0.x + r1.x) + r2.x + br4.x, (r0.y + r1.y) + r2.y + br4.y,
                   (r0.z + r1.z) + r2.z + br4.z, (r0.w + r1.w) + r2.w + br4.w};
    float hz[4] = {(z0.x + z1.x) + z2.x + bz4.x, (z0.y + z1.y) + z2.y + bz4.y,
                   (z0.z + z1.z) + z2.z + bz4.z, (z0.w + z1.w) + z2.w + bz4.w};
    float hn[4] = {(n0.x + n1.x) + n2.x + bn4.x, (n0.y + n1.y) + n2.y + bn4.y,
                   (n0.z + n1.z) + n2.z + bn4.z, (n0.w + n1.w) + n2.w + bn4.w};
    float hv[4] = {h4.x, h4.y, h4.z, h4.w};

    float hy[4], pre[4];
    __nv_bfloat16 s1[4], s2[4], s3[4];
    #pragma unroll
    for (int j = 0; j < 4; j++) {
        float r  = 1.0f/(1.0f + expf(-(ir[j]+hr[j])));
        float zz = 1.0f/(1.0f + expf(-(iz[j]+hz[j])));
        pre[j] = in_[j] + r*hn[j];
        float n = tanhf(pre[j]);
        hy[j] = n + zz*(hv[j] - n);
        split3(hy[j], s1[j], s2[j], s3[j]);
    }
    *(float4*)(g_h + i) = make_float4(hy[0], hy[1], hy[2], hy[3]);
    #pragma unroll
    for (int j = 0; j < 4; j++) { g_h1[i+j] = s1[j]; g_h2[i+j] = s2[j]; g_h3[i+j] = s3[j]; }
    size_t om = ((size_t)b*Ss + s)*Hh + hh;
    *(float4*)(g_hs + om)   = make_float4(hy[0], hy[1], hy[2], hy[3]);
    *(float4*)(out_pre + om) = make_float4(pre[0], pre[1], pre[2], pre[3]);
}

// ============================================================
// 5) output head GEMM (fp32, 128x128 tile, 8x8/thread; k-order = R5)
//    grid (4, 256)
// ============================================================
__global__ __launch_bounds__(256) void k_gemm_logits(const float* __restrict__ lw,
                                                     const float* __restrict__ lb) {
    __shared__ float As[16][128+4];
    __shared__ float Bs[16][128+4];
    int m0 = blockIdx.y * 128;
    int n0 = blockIdx.x * 128;
    int tid = threadIdx.x;
    int tx = tid & 15, ty = tid >> 4;
    float acc[8][8] = {};
    int arow = tid >> 2;
    int acol = (tid & 3) * 4;

    float4 pa[2], pb[2];
    #pragma unroll
    for (int i = 0; i < 2; i++) {
        pa[i] = *(const float4*)(g_hs + (size_t)(m0 + arow + i*64)*Hh + acol);
        pb[i] = *(const float4*)(lw + (size_t)(n0 + arow + i*64)*Hh + acol);
    }

    for (int k0 = 0; k0 < Hh; k0 += 16) {
        #pragma unroll
        for (int i = 0; i < 2; i++) {
            int rr = arow + i*64;
            As[acol+0][rr] = pa[i].x; As[acol+1][rr] = pa[i].y;
            As[acol+2][rr] = pa[i].z; As[acol+3][rr] = pa[i].w;
            Bs[acol+0][rr] = pb[i].x; Bs[acol+1][rr] = pb[i].y;
            Bs[acol+2][rr] = pb[i].z; Bs[acol+3][rr] = pb[i].w;
        }
        __syncthreads();
        if (k0 + 16 < Hh) {
            #pragma unroll
            for (int i = 0; i < 2; i++) {
                pa[i] = *(const float4*)(g_hs + (size_t)(m0 + arow + i*64)*Hh + k0 + 16 + acol);
                pb[i] = *(const float4*)(lw + (size_t)(n0 + arow + i*64)*Hh + k0 + 16 + acol);
            }
        }
        #pragma unroll
        for (int k = 0; k < 16; k++) {
            float ar[8], br[8];
            #pragma unroll
            for (int i2 = 0; i2 < 8; i2++) ar[i2] = As[k][ty*8+i2];
            #pragma unroll
            for (int j = 0; j < 8; j++)   br[j]  = Bs[k][tx*8+j];
            #pragma unroll
            for (int i2 = 0; i2 < 8; i2++)
                #pragma unroll
                for (int j = 0; j < 8; j++) acc[i2][j] += ar[i2]*br[j];
        }
        __syncthreads();
    }
    #pragma unroll
    for (int i2 = 0; i2 < 8; i2++) {
        int m = m0 + ty*8 + i2;
        #pragma unroll
        for (int j = 0; j < 8; j++) {
            int oo = n0 + tx*8 + j;
            g_logits[(size_t)m*Oo + oo] = acc[i2][j] + lb[oo];
        }
    }
}

// ============================================================
// 6) softmax + argmax one-hot (identical to R5)
// ============================================================
__global__ __launch_bounds__(128) void k_softmax(float* __restrict__ out) {
    int m = blockIdx.x;
    const float* lg = g_logits + (size_t)m*Oo;
    __shared__ float smax[128];
    __shared__ int   sidx[128];
    __shared__ float ssum[128];
    int t = threadIdx.x;
    float vmax = -1e30f; int vidx = 0;
    for (int o = t; o < Oo; o += 128) {
        float v = lg[o];
        if (v > vmax) { vmax = v; vidx = o; }
    }
    smax[t] = vmax; sidx[t] = vidx; __syncthreads();
    for (int off = 64; off; off >>= 1) {
        if (t < off) {
            if (smax[t+off] > smax[t] || (smax[t+off] == smax[t] && sidx[t+off] < sidx[t])) {
                smax[t] = smax[t+off]; sidx[t] = sidx[t+off];
            }
        }
        __syncthreads();
    }
    float rmax = smax[0]; int amax = sidx[0];
    float lsum = 0.f;
    for (int o = t; o < Oo; o += 128) lsum += expf(lg[o]-rmax);
    ssum[t] = lsum; __syncthreads();
    for (int off = 64; off; off >>= 1) {
        if (t < off) ssum[t] += ssum[t+off];
        __syncthreads();
    }
    float inv = 1.0f / ssum[0];
    float* probs = out + PROBS_OFF + (size_t)m*Oo;
    float* samp  = out + SAMP_OFF  + (size_t)m*Oo;
    for (int o = t; o < Oo; o += 128) {
        probs[o] = expf(lg[o]-rmax) * inv;
        samp[o]  = (o == amax) ? 1.0f : 0.0f;
    }
}

__global__ void k_hx(float* __restrict__ out) {
    int i = blockIdx.x * blockDim.x + threadIdx.x;
    if (i < Bb*Hh) out[i] = g_h[i];
}

// ============================================================
extern "C" void kernel_launch(void* const* d_in, const int* in_sizes, int n_in,
                              void* d_out, int out_size) {
    const float* y   = (const float*)d_in[0];
    const float* gt  = (const float*)d_in[1];
    const float* hx  = (const float*)d_in[2];
    const float* wih = (const float*)d_in[3];
    const float* bih = (const float*)d_in[4];
    const float* whh = (const float*)d_in[5];
    const float* bhh = (const float*)d_in[6];
    const float* lw  = (const float*)d_in[7];
    const float* lb  = (const float*)d_in[8];
    const float* got = (const float*)d_in[9];
    float* out = (float*)d_out;

    cudaFuncSetAttribute(k_gemm_gh_mma, cudaFuncAttributeMaxDynamicSharedMemorySize,
                         NSTAGE*STAGE_BYTES);

    k_idx<<<(Bb*Ss)/8, 256>>>(gt, got);
    k_split_w<<<(Gg*Hh)/256, 256>>>(whh);
    k_copyh<<<(Bb*Hh)/256, 256>>>(hx);
    k_gemm_gi<<<dim3(Gg/128, Ss), 256>>>(y, wih, bih);
    for (int s = 0; s < Ss; s++) {
        k_gemm_gh_mma<<<dim3(Gg/128, 3), 256, NSTAGE*STAGE_BYTES>>>();
        k_update<<<(Bb*Hh/4)/256, 256>>>(s, bhh, out + PRE_OFF);
    }
    k_gemm_logits<<<dim3(Oo/128, (Bb*Ss)/128), 256>>>(lw, lb);
    k_softmax<<<Bb*Ss, 128>>>(out);
    k_hx<<<(Bb*Hh+255)/256, 256>>>(out + HX_OFF);
}

// round 12
// speedup vs baseline: 1.2000x; 1.2000x over previous
#include <cuda_runtime.h>
#include <cuda_bf16.h>
#include <math.h>
#include <stdint.h>

#define Bb 128
#define Ss 256
#define Ii 512
#define Oo 512
#define Hh 1024
#define Gg (3*Hh)      // 3072
#define IOio (Ii+Oo)   // 1024

// ---- output layout ----
#define PROBS_OFF  0
#define PRE_OFF    ((size_t)Bb*Ss*Oo)
#define SAMP_OFF   (PRE_OFF + (size_t)Bb*Ss*Hh)
#define HX_OFF     (SAMP_OFF + (size_t)Bb*Ss*Oo)

// ---- scratch ----
__device__ int   g_idx[Bb*Ss];
__device__ float g_gi[(size_t)Ss*Bb*Gg];
__device__ float g_h[Bb*Hh];
__device__ float g_ghp[3][(size_t)Bb*Gg];
__device__ float g_hs[(size_t)Bb*Ss*Hh];
__device__ float g_logits[(size_t)Bb*Ss*Oo];
__device__ __nv_bfloat16 g_h1[Bb*Hh];
__device__ __nv_bfloat16 g_h2[Bb*Hh];
__device__ __nv_bfloat16 g_h3[Bb*Hh];
__device__ __nv_bfloat16 g_w1[(size_t)Gg*Hh];
__device__ __nv_bfloat16 g_w2[(size_t)Gg*Hh];
__device__ __nv_bfloat16 g_w3[(size_t)Gg*Hh];

// product table: seg -> (A split idx, B split idx)
__constant__ int SEG_A[6] = {0,0,1,0,2,1};
__constant__ int SEG_B[6] = {0,1,0,2,0,1};

// ============================================================
// PTX helpers
// ============================================================
__device__ __forceinline__ uint32_t smem_u32(const void* p) {
    uint32_t a;
    asm("{ .reg .u64 t; cvta.to.shared.u64 t, %1; cvt.u32.u64 %0, t; }" : "=r"(a) : "l"(p));
    return a;
}
__device__ __forceinline__ void cp16(uint32_t dst, const void* src) {
    asm volatile("cp.async.cg.shared.global [%0], [%1], 16;" :: "r"(dst), "l"(src));
}
#define CP_COMMIT() asm volatile("cp.async.commit_group;" ::: "memory")
#define CP_WAIT(n)  asm volatile("cp.async.wait_group %0;" :: "n"(n) : "memory")

__device__ __forceinline__ void ldmA(uint32_t* a, uint32_t addr) {
    asm volatile("ldmatrix.sync.aligned.m8n8.x4.shared.b16 {%0,%1,%2,%3}, [%4];"
        : "=r"(a[0]), "=r"(a[1]), "=r"(a[2]), "=r"(a[3]) : "r"(addr));
}
__device__ __forceinline__ void ldmB4(uint32_t* b, uint32_t addr) {
    asm volatile("ldmatrix.sync.aligned.m8n8.x4.shared.b16 {%0,%1,%2,%3}, [%4];"
        : "=r"(b[0]), "=r"(b[1]), "=r"(b[2]), "=r"(b[3]) : "r"(addr));
}
__device__ __forceinline__ void mma_bf16(float* c, const uint32_t* a, const uint32_t* b) {
    asm volatile("mma.sync.aligned.m16n8k16.row.col.f32.bf16.bf16.f32 "
        "{%0,%1,%2,%3}, {%4,%5,%6,%7}, {%8,%9}, {%0,%1,%2,%3};"
        : "+f"(c[0]), "+f"(c[1]), "+f"(c[2]), "+f"(c[3])
        : "r"(a[0]), "r"(a[1]), "r"(a[2]), "r"(a[3]), "r"(b[0]), "r"(b[1]));
}

#define STRD 80                      // smem row stride (64B data + 16B pad)
#define STAGE_BYTES ((128+64)*STRD)  // 15360 per pipeline stage
#define NSTAGE 5

// One BK=32 chunk, warp tile 32(M) x 16(N); 16 warps = 4M x 4N over 128x64.
// All loads hoisted ahead of all mmas; per-element K order identical to R5.
__device__ __forceinline__ void compute_chunk(uint32_t aB, uint32_t bB, int wm, int wn,
                                              int lane, float acc[2][2][4]) {
    uint32_t a[2][2][4], b[2][4];
    int t = lane >> 3, r = lane & 7;
    #pragma unroll
    for (int kk = 0; kk < 2; kk++) {
        #pragma unroll
        for (int mt = 0; mt < 2; mt++)
            ldmA(a[kk][mt], aB + (wm + mt*16 + (lane & 15))*STRD + kk*32 + ((lane >> 4) & 1)*16);
        // packed B: x4 covers 2 n-tiles (16 cols) x 2 k-halves (full-lane ldmatrix)
        ldmB4(b[kk], bB + (wn + (t >> 1)*8 + r)*STRD + kk*32 + (t & 1)*16);
    }
    #pragma unroll
    for (int kk = 0; kk < 2; kk++)
        #pragma unroll
        for (int mt = 0; mt < 2; mt++)
            #pragma unroll
            for (int nt = 0; nt < 2; nt++)
                mma_bf16(acc[mt][nt], a[kk][mt], &b[kk][nt*2]);
}

// ============================================================
// prep kernels
// ============================================================
__global__ void k_idx(const float* __restrict__ gt, const float* __restrict__ gotoken) {
    int wg   = (blockIdx.x * blockDim.x + threadIdx.x) >> 5;
    int lane = threadIdx.x & 31;
    if (wg >= Bb*Ss) return;
    int s = wg / Bb, b = wg % Bb;
    const float* src = (s == 0) ? gotoken : (gt + ((size_t)b*Ss + (s-1))*Oo);
    int found = Oo;
    for (int o = lane; o < Oo; o += 32)
        if (src[o] > 0.5f) found = min(found, o);
    #pragma unroll
    for (int off = 16; off; off >>= 1)
        found = min(found, __shfl_xor_sync(0xffffffffu, found, off));
    if (lane == 0) g_idx[wg] = found;
}

__device__ __forceinline__ void split3(float v, __nv_bfloat16& a, __nv_bfloat16& b, __nv_bfloat16& c) {
    a = __float2bfloat16(v);
    float r = v - __bfloat162float(a);
    b = __float2bfloat16(r);
    c = __float2bfloat16(r - __bfloat162float(b));
}

__global__ void k_copyh(const float* __restrict__ hx) {
    int i = blockIdx.x * blockDim.x + threadIdx.x;
    if (i < Bb*Hh) {
        float v = hx[i];
        g_h[i] = v;
        split3(v, g_h1[i], g_h2[i], g_h3[i]);
    }
}
__global__ void k_split_w(const float* __restrict__ w) {
    int i = blockIdx.x * blockDim.x + threadIdx.x;
    if (i < Gg*Hh) split3(w[i], g_w1[i], g_w2[i], g_w3[i]);
}

// ============================================================
// 2) gi GEMM (fp32, 128x64 tile, reg-prefetch; identical to R10)
// ============================================================
__global__ __launch_bounds__(256) void k_gemm_gi(const float* __restrict__ y,
                                                 const float* __restrict__ wih,
                                                 const float* __restrict__ bih) {
    __shared__ float As[16][128+4];
    __shared__ float Bs[16][64+4];
    int s  = blockIdx.y;
    int n0 = blockIdx.x * 64;
    int tid = threadIdx.x;
    int tx = tid & 15, ty = tid >> 4;
    float acc[8][4] = {};
    int arow = tid >> 2;
    int acol = (tid & 3) * 4;

    float4 pa[2], pb;
    #pragma unroll
    for (int hseg = 0; hseg < 2; hseg++)
        pa[hseg] = *(const float4*)(y + ((size_t)(arow + hseg*64)*Ss + s)*Ii + acol);
    pb = *(const float4*)(wih + (size_t)(n0 + arow)*IOio + acol);

    for (int k0 = 0; k0 < Ii; k0 += 16) {
        #pragma unroll
        for (int hseg = 0; hseg < 2; hseg++) {
            int b = arow + hseg*64;
            As[acol+0][b] = pa[hseg].x; As[acol+1][b] = pa[hseg].y;
            As[acol+2][b] = pa[hseg].z; As[acol+3][b] = pa[hseg].w;
        }
        Bs[acol+0][arow] = pb.x; Bs[acol+1][arow] = pb.y;
        Bs[acol+2][arow] = pb.z; Bs[acol+3][arow] = pb.w;
        __syncthreads();
        if (k0 + 16 < Ii) {
            #pragma unroll
            for (int hseg = 0; hseg < 2; hseg++)
                pa[hseg] = *(const float4*)(y + ((size_t)(arow + hseg*64)*Ss + s)*Ii + k0 + 16 + acol);
            pb = *(const float4*)(wih + (size_t)(n0 + arow)*IOio + k0 + 16 + acol);
        }
        #pragma unroll
        for (int k = 0; k < 16; k++) {
            float ar[8], br[4];
            #pragma unroll
            for (int i2 = 0; i2 < 8; i2++) ar[i2] = As[k][ty*8+i2];
            #pragma unroll
            for (int j = 0; j < 4; j++)   br[j]  = Bs[k][tx*4+j];
            #pragma unroll
            for (int i2 = 0; i2 < 8; i2++)
                #pragma unroll
                for (int j = 0; j < 4; j++) acc[i2][j] += ar[i2]*br[j];
        }
        __syncthreads();
    }
    #pragma unroll
    for (int i2 = 0; i2 < 8; i2++) {
        int b = ty*8 + i2;
        int m = s*Bb + b;
        int id = g_idx[m];
        #pragma unroll
        for (int j = 0; j < 4; j++) {
            int gg = n0 + tx*4 + j;
            g_gi[(size_t)m*Gg + gg] = acc[i2][j] + wih[(size_t)gg*IOio + Ii + id] + bih[gg];
        }
    }
}

// ============================================================
// 3) per-step hidden GEMM (bf16 6-product, split-K=3): grid (48,3)
//    BM=128, BN=64, BK=32; 512 threads / 16 warps (4M x 4N);
//    5-stage cp.async; per-element K order identical to R5
// ============================================================
__global__ __launch_bounds__(512) void k_gemm_gh_mma() {
    extern __shared__ __align__(16) char dyn[];
    int tid = threadIdx.x, wid = tid >> 5, lane = tid & 31;
    int n0 = blockIdx.x * 64;
    int z  = blockIdx.y;
    int wm = (wid >> 2) * 32, wn = (wid & 3) * 16;
    uint32_t sb = smem_u32(dyn);
    const __nv_bfloat16* Ahs[3] = { g_h1, g_h2, g_h3 };
    const __nv_bfloat16* Bws[3] = { g_w1, g_w2, g_w3 };

    auto issue = [&](int c) {
        int buf = c % NSTAGE;
        uint32_t aBuf = sb + buf*STAGE_BYTES;
        uint32_t bBuf = aBuf + 128*STRD;
        int cg  = z*64 + c;
        int seg = cg >> 5;
        int kl  = (cg & 31) << 5;
        const __nv_bfloat16* sa  = Ahs[SEG_A[seg]];
        const __nv_bfloat16* sbw = Bws[SEG_B[seg]];
        // A: 128 rows x 4 chunks = 512 chunks -> 1 per thread
        {
            int row = tid >> 2, q = tid & 3;
            cp16(aBuf + row*STRD + q*16, sa + (size_t)row*Hh + kl + q*8);
        }
        // B: 64 rows x 4 chunks = 256 chunks -> threads < 256
        if (tid < 256) {
            int row = tid >> 2, q = tid & 3;
            cp16(bBuf + row*STRD + q*16, sbw + (size_t)(n0 + row)*Hh + kl + q*8);
        }
    };

    float acc[2][2][4] = {};
    issue(0); CP_COMMIT();
    issue(1); CP_COMMIT();
    issue(2); CP_COMMIT();
    issue(3); CP_COMMIT();
    for (int c = 0; c < 64; c++) {
        CP_WAIT(3);
        __syncthreads();
        if (c + 4 < 64) { issue(c + 4); CP_COMMIT(); }
        int buf = c % NSTAGE;
        compute_chunk(sb + buf*STAGE_BYTES, sb + buf*STAGE_BYTES + 128*STRD, wm, wn, lane, acc);
    }

    float* dst = g_ghp[z];
    int quad = lane >> 2, tq = lane & 3;
    #pragma unroll
    for (int mt = 0; mt < 2; mt++) {
        #pragma unroll
        for (int nt = 0; nt < 2; nt++) {
            int row = wm + mt*16 + quad;
            int col = n0 + wn + nt*8 + tq*2;
            *(float2*)(dst + (size_t)row*Gg + col)     = make_float2(acc[mt][nt][0], acc[mt][nt][1]);
            *(float2*)(dst + (size_t)(row+8)*Gg + col) = make_float2(acc[mt][nt][2], acc[mt][nt][3]);
        }
    }
}

// ============================================================
// 4) per-step GRU gate update (float4 vectorized; identical to R10)
// ============================================================
__global__ __launch_bounds__(256) void k_update(int s, const float* __restrict__ bhh,
                                                float* __restrict__ out_pre) {
    int i4 = blockIdx.x * blockDim.x + threadIdx.x;
    if (i4 >= Bb*Hh/4) return;
    int i = i4 * 4;
    int b = i / Hh, hh = i % Hh;
    size_t gib = ((size_t)(s*Bb + b))*Gg + hh;
    float4 ir4 = __ldg((const float4*)(g_gi + gib));
    float4 iz4 = __ldg((const float4*)(g_gi + gib + Hh));
    float4 in4 = __ldg((const float4*)(g_gi + gib + 2*Hh));
    size_t ghb = (size_t)b*Gg + hh;
    float4 r0 = __ldcg((const float4*)(g_ghp[0] + ghb));
    float4 r1 = __ldcg((const float4*)(g_ghp[1] + ghb));
    float4 r2 = __ldcg((const float4*)(g_ghp[2] + ghb));
    float4 z0 = __ldcg((const float4*)(g_ghp[0] + ghb + Hh));
    float4 z1 = __ldcg((const float4*)(g_ghp[1] + ghb + Hh));
    float4 z2 = __ldcg((const float4*)(g_ghp[2] + ghb + Hh));
    float4 n0 = __ldcg((const float4*)(g_ghp[0] + ghb + 2*Hh));
    float4 n1 = __ldcg((const float4*)(g_ghp[1] + ghb + 2*Hh));
    float4 n2 = __ldcg((const float4*)(g_ghp[2] + ghb + 2*Hh));
    float4 br4 = __ldg((const float4*)(bhh + hh));
    float4 bz4 = __ldg((const float4*)(bhh + Hh + hh));
    float4 bn4 = __ldg((const float4*)(bhh + 2*Hh + hh));
    float4 h4  = *(const float4*)(g_h + i);

    float ir[4] = {ir4.x, ir4.y, ir4.z, ir4.w};
    float iz[4] = {iz4.x, iz4.y, iz4.z, iz4.w};
    float in_[4] = {in4.x, in4.y, in4.z, in4.w};
    float hr[4] = {(r0.x + r1.x) + r2.x + br4.x, (r0.y + r1.y) + r2.y + br4.y,
                   (r0.z + r1.z) + r2.z + br4.z, (r0.w + r1.w) + r2.w + br4.w};
    float hz[4] = {(z0.x + z1.x) + z2.x + bz4.x, (z0.y + z1.y) + z2.y + bz4.y,
                   (z0.z + z1.z) + z2.z + bz4.z, (z0.w + z1.w) + z2.w + bz4.w};
    float hn[4] = {(n0.x + n1.x) + n2.x + bn4.x, (n0.y + n1.y) + n2.y + bn4.y,
                   (n0.z + n1.z) + n2.z + bn4.z, (n0.w + n1.w) + n2.w + bn4.w};
    float hv[4] = {h4.x, h4.y, h4.z, h4.w};

    float hy[4], pre[4];
    __nv_bfloat16 s1[4], s2[4], s3[4];
    #pragma unroll
    for (int j = 0; j < 4; j++) {
        float r  = 1.0f/(1.0f + expf(-(ir[j]+hr[j])));
        float zz = 1.0f/(1.0f + expf(-(iz[j]+hz[j])));
        pre[j] = in_[j] + r*hn[j];
        float n = tanhf(pre[j]);
        hy[j] = n + zz*(hv[j] - n);
        split3(hy[j], s1[j], s2[j], s3[j]);
    }
    *(float4*)(g_h + i) = make_float4(hy[0], hy[1], hy[2], hy[3]);
    #pragma unroll
    for (int j = 0; j < 4; j++) { g_h1[i+j] = s1[j]; g_h2[i+j] = s2[j]; g_h3[i+j] = s3[j]; }
    size_t om = ((size_t)b*Ss + s)*Hh + hh;
    *(float4*)(g_hs + om)   = make_float4(hy[0], hy[1], hy[2], hy[3]);
    *(float4*)(out_pre + om) = make_float4(pre[0], pre[1], pre[2], pre[3]);
}

// ============================================================
// 5) output head GEMM (fp32, 128x64 tile, reg-prefetch; identical to R10)
// ============================================================
__global__ __launch_bounds__(256) void k_gemm_logits(const float* __restrict__ lw,
                                                     const float* __restrict__ lb) {
    __shared__ float As[16][128+4];
    __shared__ float Bs[16][64+4];
    int m0 = blockIdx.y * 128;
    int n0 = blockIdx.x * 64;
    int tid = threadIdx.x;
    int tx = tid & 15, ty = tid >> 4;
    float acc[8][4] = {};
    int arow = tid >> 2;
    int acol = (tid & 3) * 4;

    float4 pa[2], pb;
    #pragma unroll
    for (int hseg = 0; hseg < 2; hseg++)
        pa[hseg] = *(const float4*)(g_hs + (size_t)(m0 + arow + hseg*64)*Hh + acol);
    pb = *(const float4*)(lw + (size_t)(n0 + arow)*Hh + acol);

    for (int k0 = 0; k0 < Hh; k0 += 16) {
        #pragma unroll
        for (int hseg = 0; hseg < 2; hseg++) {
            int r = arow + hseg*64;
            As[acol+0][r] = pa[hseg].x; As[acol+1][r] = pa[hseg].y;
            As[acol+2][r] = pa[hseg].z; As[acol+3][r] = pa[hseg].w;
        }
        Bs[acol+0][arow] = pb.x; Bs[acol+1][arow] = pb.y;
        Bs[acol+2][arow] = pb.z; Bs[acol+3][arow] = pb.w;
        __syncthreads();
        if (k0 + 16 < Hh) {
            #pragma unroll
            for (int hseg = 0; hseg < 2; hseg++)
                pa[hseg] = *(const float4*)(g_hs + (size_t)(m0 + arow + hseg*64)*Hh + k0 + 16 + acol);
            pb = *(const float4*)(lw + (size_t)(n0 + arow)*Hh + k0 + 16 + acol);
        }
        #pragma unroll
        for (int k = 0; k < 16; k++) {
            float ar[8], br[4];
            #pragma unroll
            for (int i2 = 0; i2 < 8; i2++) ar[i2] = As[k][ty*8+i2];
            #pragma unroll
            for (int j = 0; j < 4; j++)   br[j]  = Bs[k][tx*4+j];
            #pragma unroll
            for (int i2 = 0; i2 < 8; i2++)
                #pragma unroll
                for (int j = 0; j < 4; j++) acc[i2][j] += ar[i2]*br[j];
        }
        __syncthreads();
    }
    #pragma unroll
    for (int i2 = 0; i2 < 8; i2++) {
        int m = m0 + ty*8 + i2;
        #pragma unroll
        for (int j = 0; j < 4; j++) {
            int oo = n0 + tx*4 + j;
            g_logits[(size_t)m*Oo + oo] = acc[i2][j] + lb[oo];
        }
    }
}

// ============================================================
// 6) softmax + argmax one-hot (identical to R5)
// ============================================================
__global__ __launch_bounds__(128) void k_softmax(float* __restrict__ out) {
    int m = blockIdx.x;
    const float* lg = g_logits + (size_t)m*Oo;
    __shared__ float smax[128];
    __shared__ int   sidx[128];
    __shared__ float ssum[128];
    int t = threadIdx.x;
    float vmax = -1e30f; int vidx = 0;
    for (int o = t; o < Oo; o += 128) {
        float v = lg[o];
        if (v > vmax) { vmax = v; vidx = o; }
    }
    smax[t] = vmax; sidx[t] = vidx; __syncthreads();
    for (int off = 64; off; off >>= 1) {
        if (t < off) {
            if (smax[t+off] > smax[t] || (smax[t+off] == smax[t] && sidx[t+off] < sidx[t])) {
                smax[t] = smax[t+off]; sidx[t] = sidx[t+off];
            }
        }
        __syncthreads();
    }
    float rmax = smax[0]; int amax = sidx[0];
    float lsum = 0.f;
    for (int o = t; o < Oo; o += 128) lsum += expf(lg[o]-rmax);
    ssum[t] = lsum; __syncthreads();
    for (int off = 64; off; off >>= 1) {
        if (t < off) ssum[t] += ssum[t+off];
        __syncthreads();
    }
    float inv = 1.0f / ssum[0];
    float* probs = out + PROBS_OFF + (size_t)m*Oo;
    float* samp  = out + SAMP_OFF  + (size_t)m*Oo;
    for (int o = t; o < Oo; o += 128) {
        probs[o] = expf(lg[o]-rmax) * inv;
        samp[o]  = (o == amax) ? 1.0f : 0.0f;
    }
}

__global__ void k_hx(float* __restrict__ out) {
    int i = blockIdx.x * blockDim.x + threadIdx.x;
    if (i < Bb*Hh) out[i] = g_h[i];
}

// ============================================================
extern "C" void kernel_launch(void* const* d_in, const int* in_sizes, int n_in,
                              void* d_out, int out_size) {
    const float* y   = (const float*)d_in[0];
    const float* gt  = (const float*)d_in[1];
    const float* hx  = (const float*)d_in[2];
    const float* wih = (const float*)d_in[3];
    const float* bih = (const float*)d_in[4];
    const float* whh = (const float*)d_in[5];
    const float* bhh = (const float*)d_in[6];
    const float* lw  = (const float*)d_in[7];
    const float* lb  = (const float*)d_in[8];
    const float* got = (const float*)d_in[9];
    float* out = (float*)d_out;

    cudaFuncSetAttribute(k_gemm_gh_mma, cudaFuncAttributeMaxDynamicSharedMemorySize,
                         NSTAGE*STAGE_BYTES);

    k_idx<<<(Bb*Ss)/8, 256>>>(gt, got);
    k_split_w<<<(Gg*Hh)/256, 256>>>(whh);
    k_copyh<<<(Bb*Hh)/256, 256>>>(hx);
    k_gemm_gi<<<dim3(Gg/64, Ss), 256>>>(y, wih, bih);
    for (int s = 0; s < Ss; s++) {
        k_gemm_gh_mma<<<dim3(Gg/64, 3), 512, NSTAGE*STAGE_BYTES>>>();
        k_update<<<(Bb*Hh/4)/256, 256>>>(s, bhh, out + PRE_OFF);
    }
    k_gemm_logits<<<dim3(Oo/64, (Bb*Ss)/128), 256>>>(lw, lb);
    k_softmax<<<Bb*Ss, 128>>>(out);
    k_hx<<<(Bb*Hh+255)/256, 256>>>(out + HX_OFF);
}

// round 13
// speedup vs baseline: 1.3678x; 1.1399x over previous
#include <cuda_runtime.h>
#include <cuda_bf16.h>
#include <math.h>
#include <stdint.h>

#define Bb 128
#define Ss 256
#define Ii 512
#define Oo 512
#define Hh 1024
#define Gg (3*Hh)      // 3072
#define IOio (Ii+Oo)   // 1024

// ---- output layout ----
#define PROBS_OFF  0
#define PRE_OFF    ((size_t)Bb*Ss*Oo)
#define SAMP_OFF   (PRE_OFF + (size_t)Bb*Ss*Hh)
#define HX_OFF     (SAMP_OFF + (size_t)Bb*Ss*Oo)

// ---- scratch ----
__device__ int   g_idx[Bb*Ss];
__device__ float g_gi[(size_t)Ss*Bb*Gg];
__device__ float g_h[Bb*Hh];
__device__ float g_ghp[3][(size_t)Bb*Gg];
__device__ float g_hs[(size_t)Bb*Ss*Hh];
__device__ float g_logits[(size_t)Bb*Ss*Oo];
__device__ __nv_bfloat16 g_h1[Bb*Hh];
__device__ __nv_bfloat16 g_h2[Bb*Hh];
__device__ __nv_bfloat16 g_h3[Bb*Hh];
__device__ __nv_bfloat16 g_w1[(size_t)Gg*Hh];
__device__ __nv_bfloat16 g_w2[(size_t)Gg*Hh];
__device__ __nv_bfloat16 g_w3[(size_t)Gg*Hh];

// product table: seg -> (A split idx, B split idx)
__constant__ int SEG_A[6] = {0,0,1,0,2,1};
__constant__ int SEG_B[6] = {0,1,0,2,0,1};

// ============================================================
// PTX helpers
// ============================================================
__device__ __forceinline__ uint32_t smem_u32(const void* p) {
    uint32_t a;
    asm("{ .reg .u64 t; cvta.to.shared.u64 t, %1; cvt.u32.u64 %0, t; }" : "=r"(a) : "l"(p));
    return a;
}
__device__ __forceinline__ void cp16(uint32_t dst, const void* src) {
    asm volatile("cp.async.cg.shared.global [%0], [%1], 16;" :: "r"(dst), "l"(src));
}
#define CP_COMMIT() asm volatile("cp.async.commit_group;" ::: "memory")
#define CP_WAIT(n)  asm volatile("cp.async.wait_group %0;" :: "n"(n) : "memory")

__device__ __forceinline__ void ldmA(uint32_t* a, uint32_t addr) {
    asm volatile("ldmatrix.sync.aligned.m8n8.x4.shared.b16 {%0,%1,%2,%3}, [%4];"
        : "=r"(a[0]), "=r"(a[1]), "=r"(a[2]), "=r"(a[3]) : "r"(addr));
}
__device__ __forceinline__ void ldmB4(uint32_t* b, uint32_t addr) {
    asm volatile("ldmatrix.sync.aligned.m8n8.x4.shared.b16 {%0,%1,%2,%3}, [%4];"
        : "=r"(b[0]), "=r"(b[1]), "=r"(b[2]), "=r"(b[3]) : "r"(addr));
}
__device__ __forceinline__ void mma_bf16(float* c, const uint32_t* a, const uint32_t* b) {
    asm volatile("mma.sync.aligned.m16n8k16.row.col.f32.bf16.bf16.f32 "
        "{%0,%1,%2,%3}, {%4,%5,%6,%7}, {%8,%9}, {%0,%1,%2,%3};"
        : "+f"(c[0]), "+f"(c[1]), "+f"(c[2]), "+f"(c[3])
        : "r"(a[0]), "r"(a[1]), "r"(a[2]), "r"(a[3]), "r"(b[0]), "r"(b[1]));
}

#define STRD 80                      // smem row stride (64B data + 16B pad)
#define STAGE_BYTES ((128+64)*STRD)  // 15360 per chunk buffer
#define NBUF 6                       // 3 pairs x 2 chunks

// One BK=32 chunk, warp tile 32(M) x 32(N); 8 warps = 4M x 2N over 128x64.
// All loads hoisted ahead of all mmas; per-element K order identical to R5.
__device__ __forceinline__ void compute_chunk(uint32_t aB, uint32_t bB, int wm, int wn,
                                              int lane, float acc[2][4][4]) {
    uint32_t a[2][2][4], b[2][2][4];
    int t = lane >> 3, r = lane & 7;
    #pragma unroll
    for (int kk = 0; kk < 2; kk++) {
        #pragma unroll
        for (int mt = 0; mt < 2; mt++)
            ldmA(a[kk][mt], aB + (wm + mt*16 + (lane & 15))*STRD + kk*32 + ((lane >> 4) & 1)*16);
        // packed B: x4 covers 2 n-tiles x 2 k-halves (full-lane ldmatrix)
        #pragma unroll
        for (int ldi = 0; ldi < 2; ldi++)
            ldmB4(b[kk][ldi], bB + (wn + ldi*16 + (t >> 1)*8 + r)*STRD + kk*32 + (t & 1)*16);
    }
    #pragma unroll
    for (int kk = 0; kk < 2; kk++)
        #pragma unroll
        for (int mt = 0; mt < 2; mt++)
            #pragma unroll
            for (int nt = 0; nt < 4; nt++)
                mma_bf16(acc[mt][nt], a[kk][mt], &b[kk][nt >> 1][(nt & 1)*2]);
}

// ============================================================
// prep kernels
// ============================================================
__global__ void k_idx(const float* __restrict__ gt, const float* __restrict__ gotoken) {
    int wg   = (blockIdx.x * blockDim.x + threadIdx.x) >> 5;
    int lane = threadIdx.x & 31;
    if (wg >= Bb*Ss) return;
    int s = wg / Bb, b = wg % Bb;
    const float* src = (s == 0) ? gotoken : (gt + ((size_t)b*Ss + (s-1))*Oo);
    int found = Oo;
    for (int o = lane; o < Oo; o += 32)
        if (src[o] > 0.5f) found = min(found, o);
    #pragma unroll
    for (int off = 16; off; off >>= 1)
        found = min(found, __shfl_xor_sync(0xffffffffu, found, off));
    if (lane == 0) g_idx[wg] = found;
}

__device__ __forceinline__ void split3(float v, __nv_bfloat16& a, __nv_bfloat16& b, __nv_bfloat16& c) {
    a = __float2bfloat16(v);
    float r = v - __bfloat162float(a);
    b = __float2bfloat16(r);
    c = __float2bfloat16(r - __bfloat162float(b));
}

__global__ void k_copyh(const float* __restrict__ hx) {
    int i = blockIdx.x * blockDim.x + threadIdx.x;
    if (i < Bb*Hh) {
        float v = hx[i];
        g_h[i] = v;
        split3(v, g_h1[i], g_h2[i], g_h3[i]);
    }
}
__global__ void k_split_w(const float* __restrict__ w) {
    int i = blockIdx.x * blockDim.x + threadIdx.x;
    if (i < Gg*Hh) split3(w[i], g_w1[i], g_w2[i], g_w3[i]);
}

// ============================================================
// 2) gi GEMM (fp32, 128x64 tile, reg-prefetch; identical to R10)
// ============================================================
__global__ __launch_bounds__(256) void k_gemm_gi(const float* __restrict__ y,
                                                 const float* __restrict__ wih,
                                                 const float* __restrict__ bih) {
    __shared__ float As[16][128+4];
    __shared__ float Bs[16][64+4];
    int s  = blockIdx.y;
    int n0 = blockIdx.x * 64;
    int tid = threadIdx.x;
    int tx = tid & 15, ty = tid >> 4;
    float acc[8][4] = {};
    int arow = tid >> 2;
    int acol = (tid & 3) * 4;

    float4 pa[2], pb;
    #pragma unroll
    for (int hseg = 0; hseg < 2; hseg++)
        pa[hseg] = *(const float4*)(y + ((size_t)(arow + hseg*64)*Ss + s)*Ii + acol);
    pb = *(const float4*)(wih + (size_t)(n0 + arow)*IOio + acol);

    for (int k0 = 0; k0 < Ii; k0 += 16) {
        #pragma unroll
        for (int hseg = 0; hseg < 2; hseg++) {
            int b = arow + hseg*64;
            As[acol+0][b] = pa[hseg].x; As[acol+1][b] = pa[hseg].y;
            As[acol+2][b] = pa[hseg].z; As[acol+3][b] = pa[hseg].w;
        }
        Bs[acol+0][arow] = pb.x; Bs[acol+1][arow] = pb.y;
        Bs[acol+2][arow] = pb.z; Bs[acol+3][arow] = pb.w;
        __syncthreads();
        if (k0 + 16 < Ii) {
            #pragma unroll
            for (int hseg = 0; hseg < 2; hseg++)
                pa[hseg] = *(const float4*)(y + ((size_t)(arow + hseg*64)*Ss + s)*Ii + k0 + 16 + acol);
            pb = *(const float4*)(wih + (size_t)(n0 + arow)*IOio + k0 + 16 + acol);
        }
        #pragma unroll
        for (int k = 0; k < 16; k++) {
            float ar[8], br[4];
            #pragma unroll
            for (int i2 = 0; i2 < 8; i2++) ar[i2] = As[k][ty*8+i2];
            #pragma unroll
            for (int j = 0; j < 4; j++)   br[j]  = Bs[k][tx*4+j];
            #pragma unroll
            for (int i2 = 0; i2 < 8; i2++)
                #pragma unroll
                for (int j = 0; j < 4; j++) acc[i2][j] += ar[i2]*br[j];
        }
        __syncthreads();
    }
    #pragma unroll
    for (int i2 = 0; i2 < 8; i2++) {
        int b = ty*8 + i2;
        int m = s*Bb + b;
        int id = g_idx[m];
        #pragma unroll
        for (int j = 0; j < 4; j++) {
            int gg = n0 + tx*4 + j;
            g_gi[(size_t)m*Gg + gg] = acc[i2][j] + wih[(size_t)gg*IOio + Ii + id] + bih[gg];
        }
    }
}

// ============================================================
// 3) per-step hidden GEMM (bf16 6-product, split-K=3): grid (48,3)
//    BM=128, BN=64; 256 thr / 8 warps (4M x 2N, warp tile 32x32);
//    PAIRED pipeline: one commit/wait/sync per 2 chunks (BK=64 beat),
//    6 chunk buffers. Per-element K order identical to R5.
// ============================================================
__global__ __launch_bounds__(256) void k_gemm_gh_mma() {
    extern __shared__ __align__(16) char dyn[];
    int tid = threadIdx.x, wid = tid >> 5, lane = tid & 31;
    int n0 = blockIdx.x * 64;
    int z  = blockIdx.y;
    int wm = (wid >> 1) * 32, wn = (wid & 1) * 32;
    uint32_t sb = smem_u32(dyn);
    const __nv_bfloat16* Ahs[3] = { g_h1, g_h2, g_h3 };
    const __nv_bfloat16* Bws[3] = { g_w1, g_w2, g_w3 };

    auto issue = [&](int c) {
        uint32_t aBuf = sb + (c % NBUF)*STAGE_BYTES;
        uint32_t bBuf = aBuf + 128*STRD;
        int cg  = z*64 + c;
        int seg = cg >> 5;
        int kl  = (cg & 31) << 5;
        const __nv_bfloat16* sa  = Ahs[SEG_A[seg]];
        const __nv_bfloat16* sbw = Bws[SEG_B[seg]];
        #pragma unroll
        for (int i = 0; i < 2; i++) {
            int idx = i*256 + tid;
            int row = idx >> 2, q = idx & 3;
            cp16(aBuf + row*STRD + q*16, sa + (size_t)row*Hh + kl + q*8);
        }
        {
            int row = tid >> 2, q = tid & 3;
            cp16(bBuf + row*STRD + q*16, sbw + (size_t)(n0 + row)*Hh + kl + q*8);
        }
    };

    float acc[2][4][4] = {};
    issue(0); issue(1); CP_COMMIT();      // pair 0
    issue(2); issue(3); CP_COMMIT();      // pair 1
    for (int p = 0; p < 32; p++) {
        if (p == 31) { CP_WAIT(0); } else { CP_WAIT(1); }
        __syncthreads();
        if (p + 2 < 32) { issue(2*p + 4); issue(2*p + 5); CP_COMMIT(); }
        uint32_t b0 = sb + ((2*p)     % NBUF)*STAGE_BYTES;
        uint32_t b1 = sb + ((2*p + 1) % NBUF)*STAGE_BYTES;
        compute_chunk(b0, b0 + 128*STRD, wm, wn, lane, acc);
        compute_chunk(b1, b1 + 128*STRD, wm, wn, lane, acc);
    }

    float* dst = g_ghp[z];
    int quad = lane >> 2, tq = lane & 3;
    #pragma unroll
    for (int mt = 0; mt < 2; mt++) {
        #pragma unroll
        for (int nt = 0; nt < 4; nt++) {
            int row = wm + mt*16 + quad;
            int col = n0 + wn + nt*8 + tq*2;
            *(float2*)(dst + (size_t)row*Gg + col)     = make_float2(acc[mt][nt][0], acc[mt][nt][1]);
            *(float2*)(dst + (size_t)(row+8)*Gg + col) = make_float2(acc[mt][nt][2], acc[mt][nt][3]);
        }
    }
}

// ============================================================
// 4) per-step GRU gate update (float4 vectorized; identical to R10)
// ============================================================
__global__ __launch_bounds__(256) void k_update(int s, const float* __restrict__ bhh,
                                                float* __restrict__ out_pre) {
    int i4 = blockIdx.x * blockDim.x + threadIdx.x;
    if (i4 >= Bb*Hh/4) return;
    int i = i4 * 4;
    int b = i / Hh, hh = i % Hh;
    size_t gib = ((size_t)(s*Bb + b))*Gg + hh;
    float4 ir4 = __ldg((const float4*)(g_gi + gib));
    float4 iz4 = __ldg((const float4*)(g_gi + gib + Hh));
    float4 in4 = __ldg((const float4*)(g_gi + gib + 2*Hh));
    size_t ghb = (size_t)b*Gg + hh;
    float4 r0 = __ldcg((const float4*)(g_ghp[0] + ghb));
    float4 r1 = __ldcg((const float4*)(g_ghp[1] + ghb));
    float4 r2 = __ldcg((const float4*)(g_ghp[2] + ghb));
    float4 z0 = __ldcg((const float4*)(g_ghp[0] + ghb + Hh));
    float4 z1 = __ldcg((const float4*)(g_ghp[1] + ghb + Hh));
    float4 z2 = __ldcg((const float4*)(g_ghp[2] + ghb + Hh));
    float4 n0 = __ldcg((const float4*)(g_ghp[0] + ghb + 2*Hh));
    float4 n1 = __ldcg((const float4*)(g_ghp[1] + ghb + 2*Hh));
    float4 n2 = __ldcg((const float4*)(g_ghp[2] + ghb + 2*Hh));
    float4 br4 = __ldg((const float4*)(bhh + hh));
    float4 bz4 = __ldg((const float4*)(bhh + Hh + hh));
    float4 bn4 = __ldg((const float4*)(bhh + 2*Hh + hh));
    float4 h4  = *(const float4*)(g_h + i);

    float ir[4] = {ir4.x, ir4.y, ir4.z, ir4.w};
    float iz[4] = {iz4.x, iz4.y, iz4.z, iz4.w};
    float in_[4] = {in4.x, in4.y, in4.z, in4.w};
    float hr[4] = {(r0.x + r1.x) + r2.x + br4.x, (r0.y + r1.y) + r2.y + br4.y,
                   (r0.z + r1.z) + r2.z + br4.z, (r0.w + r1.w) + r2.w + br4.w};
    float hz[4] = {(z0.x + z1.x) + z2.x + bz4.x, (z0.y + z1.y) + z2.y + bz4.y,
                   (z0.z + z1.z) + z2.z + bz4.z, (z0.w + z1.w) + z2.w + bz4.w};
    float hn[4] = {(n0.x + n1.x) + n2.x + bn4.x, (n0.y + n1.y) + n2.y + bn4.y,
                   (n0.z + n1.z) + n2.z + bn4.z, (n0.w + n1.w) + n2.w + bn4.w};
    float hv[4] = {h4.x, h4.y, h4.z, h4.w};

    float hy[4], pre[4];
    __nv_bfloat16 s1[4], s2[4], s3[4];
    #pragma unroll
    for (int j = 0; j < 4; j++) {
        float r  = 1.0f/(1.0f + expf(-(ir[j]+hr[j])));
        float zz = 1.0f/(1.0f + expf(-(iz[j]+hz[j])));
        pre[j] = in_[j] + r*hn[j];
        float n = tanhf(pre[j]);
        hy[j] = n + zz*(hv[j] - n);
        split3(hy[j], s1[j], s2[j], s3[j]);
    }
    *(float4*)(g_h + i) = make_float4(hy[0], hy[1], hy[2], hy[3]);
    #pragma unroll
    for (int j = 0; j < 4; j++) { g_h1[i+j] = s1[j]; g_h2[i+j] = s2[j]; g_h3[i+j] = s3[j]; }
    size_t om = ((size_t)b*Ss + s)*Hh + hh;
    *(float4*)(g_hs + om)   = make_float4(hy[0], hy[1], hy[2], hy[3]);
    *(float4*)(out_pre + om) = make_float4(pre[0], pre[1], pre[2], pre[3]);
}

// ============================================================
// 5) output head GEMM (fp32, 128x64 tile, reg-prefetch; identical to R10)
// ============================================================
__global__ __launch_bounds__(256) void k_gemm_logits(const float* __restrict__ lw,
                                                     const float* __restrict__ lb) {
    __shared__ float As[16][128+4];
    __shared__ float Bs[16][64+4];
    int m0 = blockIdx.y * 128;
    int n0 = blockIdx.x * 64;
    int tid = threadIdx.x;
    int tx = tid & 15, ty = tid >> 4;
    float acc[8][4] = {};
    int arow = tid >> 2;
    int acol = (tid & 3) * 4;

    float4 pa[2], pb;
    #pragma unroll
    for (int hseg = 0; hseg < 2; hseg++)
        pa[hseg] = *(const float4*)(g_hs + (size_t)(m0 + arow + hseg*64)*Hh + acol);
    pb = *(const float4*)(lw + (size_t)(n0 + arow)*Hh + acol);

    for (int k0 = 0; k0 < Hh; k0 += 16) {
        #pragma unroll
        for (int hseg = 0; hseg < 2; hseg++) {
            int r = arow + hseg*64;
            As[acol+0][r] = pa[hseg].x; As[acol+1][r] = pa[hseg].y;
            As[acol+2][r] = pa[hseg].z; As[acol+3][r] = pa[hseg].w;
        }
        Bs[acol+0][arow] = pb.x; Bs[acol+1][arow] = pb.y;
        Bs[acol+2][arow] = pb.z; Bs[acol+3][arow] = pb.w;
        __syncthreads();
        if (k0 + 16 < Hh) {
            #pragma unroll
            for (int hseg = 0; hseg < 2; hseg++)
                pa[hseg] = *(const float4*)(g_hs + (size_t)(m0 + arow + hseg*64)*Hh + k0 + 16 + acol);
            pb = *(const float4*)(lw + (size_t)(n0 + arow)*Hh + k0 + 16 + acol);
        }
        #pragma unroll
        for (int k = 0; k < 16; k++) {
            float ar[8], br[4];
            #pragma unroll
            for (int i2 = 0; i2 < 8; i2++) ar[i2] = As[k][ty*8+i2];
            #pragma unroll
            for (int j = 0; j < 4; j++)   br[j]  = Bs[k][tx*4+j];
            #pragma unroll
            for (int i2 = 0; i2 < 8; i2++)
                #pragma unroll
                for (int j = 0; j < 4; j++) acc[i2][j] += ar[i2]*br[j];
        }
        __syncthreads();
    }
    #pragma unroll
    for (int i2 = 0; i2 < 8; i2++) {
        int m = m0 + ty*8 + i2;
        #pragma unroll
        for (int j = 0; j < 4; j++) {
            int oo = n0 + tx*4 + j;
            g_logits[(size_t)m*Oo + oo] = acc[i2][j] + lb[oo];
        }
    }
}

// ============================================================
// 6) softmax + argmax one-hot (identical to R5)
// ============================================================
__global__ __launch_bounds__(128) void k_softmax(float* __restrict__ out) {
    int m = blockIdx.x;
    const float* lg = g_logits + (size_t)m*Oo;
    __shared__ float smax[128];
    __shared__ int   sidx[128];
    __shared__ float ssum[128];
    int t = threadIdx.x;
    float vmax = -1e30f; int vidx = 0;
    for (int o = t; o < Oo; o += 128) {
        float v = lg[o];
        if (v > vmax) { vmax = v; vidx = o; }
    }
    smax[t] = vmax; sidx[t] = vidx; __syncthreads();
    for (int off = 64; off; off >>= 1) {
        if (t < off) {
            if (smax[t+off] > smax[t] || (smax[t+off] == smax[t] && sidx[t+off] < sidx[t])) {
                smax[t] = smax[t+off]; sidx[t] = sidx[t+off];
            }
        }
        __syncthreads();
    }
    float rmax = smax[0]; int amax = sidx[0];
    float lsum = 0.f;
    for (int o = t; o < Oo; o += 128) lsum += expf(lg[o]-rmax);
    ssum[t] = lsum; __syncthreads();
    for (int off = 64; off; off >>= 1) {
        if (t < off) ssum[t] += ssum[t+off];
        __syncthreads();
    }
    float inv = 1.0f / ssum[0];
    float* probs = out + PROBS_OFF + (size_t)m*Oo;
    float* samp  = out + SAMP_OFF  + (size_t)m*Oo;
    for (int o = t; o < Oo; o += 128) {
        probs[o] = expf(lg[o]-rmax) * inv;
        samp[o]  = (o == amax) ? 1.0f : 0.0f;
    }
}

__global__ void k_hx(float* __restrict__ out) {
    int i = blockIdx.x * blockDim.x + threadIdx.x;
    if (i < Bb*Hh) out[i] = g_h[i];
}

// ============================================================
extern "C" void kernel_launch(void* const* d_in, const int* in_sizes, int n_in,
                              void* d_out, int out_size) {
    const float* y   = (const float*)d_in[0];
    const float* gt  = (const float*)d_in[1];
    const float* hx  = (const float*)d_in[2];
    const float* wih = (const float*)d_in[3];
    const float* bih = (const float*)d_in[4];
    const float* whh = (const float*)d_in[5];
    const float* bhh = (const float*)d_in[6];
    const float* lw  = (const float*)d_in[7];
    const float* lb  = (const float*)d_in[8];
    const float* got = (const float*)d_in[9];
    float* out = (float*)d_out;

    cudaFuncSetAttribute(k_gemm_gh_mma, cudaFuncAttributeMaxDynamicSharedMemorySize,
                         NBUF*STAGE_BYTES);

    k_idx<<<(Bb*Ss)/8, 256>>>(gt, got);
    k_split_w<<<(Gg*Hh)/256, 256>>>(whh);
    k_copyh<<<(Bb*Hh)/256, 256>>>(hx);
    k_gemm_gi<<<dim3(Gg/64, Ss), 256>>>(y, wih, bih);
    for (int s = 0; s < Ss; s++) {
        k_gemm_gh_mma<<<dim3(Gg/64, 3), 256, NBUF*STAGE_BYTES>>>();
        k_update<<<(Bb*Hh/4)/256, 256>>>(s, bhh, out + PRE_OFF);
    }
    k_gemm_logits<<<dim3(Oo/64, (Bb*Ss)/128), 256>>>(lw, lb);
    k_softmax<<<Bb*Ss, 128>>>(out);
    k_hx<<<(Bb*Hh+255)/256, 256>>>(out + HX_OFF);
}